// round 2
// baseline (speedup 1.0000x reference)
#include <cuda_runtime.h>

#define DM   1024
#define NH   16
#define DK   64
#define BATCH 2
#define SEQ  2048
#define MROWS (BATCH*SEQ)   // 4096
#define GP   68             // smem row pitch (floats): 16B-aligned rows, low-conflict

// Scratch (sanctioned __device__ globals; no allocation in kernel_launch)
__device__ float g_Q[BATCH*NH*SEQ*DK];
__device__ float g_K[BATCH*NH*SEQ*DK];
__device__ float g_V[BATCH*NH*SEQ*DK];
__device__ float g_ctx[MROWS*DM];

// ---------------------------------------------------------------------------
// GEMM: C[m][n] = sum_k A[m][k] * W[n][k] + bias[n]
// A row-major [M, DM], W row-major [DM_out=1024, DM], 64x64 tile, 256 threads,
// 4x4 register micro-tile, both operands stored k-transposed in smem so the
// inner loop is two float4 LDS + 16 FFMA.
// head_layout=1: write C to head-split [b, h, s, d] scratch (n tile == head).
// ---------------------------------------------------------------------------
__global__ __launch_bounds__(256)
void gemm_proj(const float* __restrict__ A, const float* __restrict__ W,
               const float* __restrict__ bias, float* __restrict__ C,
               int head_layout)
{
    __shared__ __align__(16) float As[64*GP]; // As[k*GP + m]
    __shared__ __align__(16) float Bs[64*GP]; // Bs[k*GP + n]

    const int m0 = blockIdx.y * 64;
    const int n0 = blockIdx.x * 64;
    const int tid = threadIdx.x;
    const int tx = tid & 15;   // n direction (4 cols each)
    const int ty = tid >> 4;   // m direction (4 rows each)

    float acc[4][4];
#pragma unroll
    for (int i = 0; i < 4; i++)
#pragma unroll
        for (int j = 0; j < 4; j++) acc[i][j] = 0.f;

    for (int kt = 0; kt < DM; kt += 64) {
#pragma unroll
        for (int i = 0; i < 16; i++) {
            int idx = tid + i * 256;
            int r = idx >> 6, k = idx & 63;
            As[k*GP + r] = A[(size_t)(m0 + r) * DM + kt + k];
            Bs[k*GP + r] = W[(size_t)(n0 + r) * DM + kt + k];
        }
        __syncthreads();
#pragma unroll 8
        for (int k = 0; k < 64; k++) {
            float4 av = *(const float4*)&As[k*GP + ty*4];
            float4 bv = *(const float4*)&Bs[k*GP + tx*4];
            float a[4] = {av.x, av.y, av.z, av.w};
            float b[4] = {bv.x, bv.y, bv.z, bv.w};
#pragma unroll
            for (int i = 0; i < 4; i++)
#pragma unroll
                for (int j = 0; j < 4; j++)
                    acc[i][j] = fmaf(a[i], b[j], acc[i][j]);
        }
        __syncthreads();
    }

    // epilogue: bias + store
#pragma unroll
    for (int i = 0; i < 4; i++) {
        int m = m0 + ty*4 + i;
        float4 v;
        v.x = acc[i][0] + bias[n0 + tx*4 + 0];
        v.y = acc[i][1] + bias[n0 + tx*4 + 1];
        v.z = acc[i][2] + bias[n0 + tx*4 + 2];
        v.w = acc[i][3] + bias[n0 + tx*4 + 3];
        if (head_layout) {
            int h = n0 >> 6;          // BN==DK==64 -> one head per n-tile
            int b = m >> 11;          // /SEQ
            int s = m & (SEQ - 1);
            *(float4*)&C[(((size_t)(b*NH + h) * SEQ + s) * DK) + tx*4] = v;
        } else {
            *(float4*)&C[(size_t)m * DM + n0 + tx*4] = v;
        }
    }
}

// ---------------------------------------------------------------------------
// Flash attention, fp32. One block = 64 query rows of one (b,h).
// Online softmax; K-tile and V-tile share one smem buffer (phase-separated).
// Scale 1/sqrt(dk) folded into the Q tile load.
// ctx written in [b, s, h, d] layout == concat layout for the out projection.
// ---------------------------------------------------------------------------
extern __shared__ float attn_smem[];

__global__ __launch_bounds__(256)
void attn_kernel(const float* __restrict__ Q, const float* __restrict__ K,
                 const float* __restrict__ V, float* __restrict__ ctx)
{
    float* Qs = attn_smem;            // [d][r]  Qs[d*GP + r]   (pre-scaled)
    float* KV = attn_smem + 64*GP;    // K phase: [d][c]; V phase: [s][d]
    float* Ps = attn_smem + 2*64*GP;  // [s][r]  P transposed

    const int bh = blockIdx.y;
    const int q0 = blockIdx.x * 64;
    const size_t base = (size_t)bh * SEQ * DK;
    const int tid = threadIdx.x;
    const int tx = tid & 15;
    const int ty = tid >> 4;

    // Load Q tile transposed, folding in softmax scale (1/8)
#pragma unroll
    for (int i = 0; i < 16; i++) {
        int idx = tid + i * 256;
        int r = idx >> 6, d = idx & 63;
        Qs[d*GP + r] = 0.125f * Q[base + (size_t)(q0 + r) * DK + d];
    }

    float mrow[4], lrow[4], accO[4][4];
#pragma unroll
    for (int i = 0; i < 4; i++) {
        mrow[i] = -1e30f; lrow[i] = 0.f;
#pragma unroll
        for (int j = 0; j < 4; j++) accO[i][j] = 0.f;
    }

    for (int s0 = 0; s0 < SEQ; s0 += 64) {
        __syncthreads();  // prev GEMM2 done with KV/Ps; also fences Q load (iter 0)

        // K tile transposed: KV[d][c]
#pragma unroll
        for (int i = 0; i < 16; i++) {
            int idx = tid + i * 256;
            int c = idx >> 6, d = idx & 63;
            KV[d*GP + c] = K[base + (size_t)(s0 + c) * DK + d];
        }
        __syncthreads();

        // S = (Q*scale) . K^T
        float sacc[4][4];
#pragma unroll
        for (int i = 0; i < 4; i++)
#pragma unroll
            for (int j = 0; j < 4; j++) sacc[i][j] = 0.f;
#pragma unroll 8
        for (int k = 0; k < 64; k++) {
            float4 qv = *(const float4*)&Qs[k*GP + ty*4];
            float4 kv = *(const float4*)&KV[k*GP + tx*4];
            float a[4] = {qv.x, qv.y, qv.z, qv.w};
            float b[4] = {kv.x, kv.y, kv.z, kv.w};
#pragma unroll
            for (int i = 0; i < 4; i++)
#pragma unroll
                for (int j = 0; j < 4; j++)
                    sacc[i][j] = fmaf(a[i], b[j], sacc[i][j]);
        }

        // online softmax (row groups = 16 contiguous lanes in a warp)
        float alpha[4];
#pragma unroll
        for (int i = 0; i < 4; i++) {
            float tm = fmaxf(fmaxf(sacc[i][0], sacc[i][1]),
                             fmaxf(sacc[i][2], sacc[i][3]));
#pragma unroll
            for (int mk = 1; mk < 16; mk <<= 1)
                tm = fmaxf(tm, __shfl_xor_sync(0xffffffffu, tm, mk));
            float mn = fmaxf(mrow[i], tm);
            alpha[i] = __expf(mrow[i] - mn);
            mrow[i] = mn;
            float rs = 0.f;
#pragma unroll
            for (int j = 0; j < 4; j++) {
                float p = __expf(sacc[i][j] - mn);
                sacc[i][j] = p;
                rs += p;
            }
#pragma unroll
            for (int mk = 1; mk < 16; mk <<= 1)
                rs += __shfl_xor_sync(0xffffffffu, rs, mk);
            lrow[i] = lrow[i] * alpha[i] + rs;
#pragma unroll
            for (int j = 0; j < 4; j++) accO[i][j] *= alpha[i];
        }

        // store P transposed: Ps[s][r]
#pragma unroll
        for (int j = 0; j < 4; j++) {
            float4 pv = make_float4(sacc[0][j], sacc[1][j], sacc[2][j], sacc[3][j]);
            *(float4*)&Ps[(tx*4 + j)*GP + ty*4] = pv;
        }
        __syncthreads();  // K reads + P writes complete

        // V tile natural layout: KV[s][d]
#pragma unroll
        for (int i = 0; i < 16; i++) {
            int idx = tid + i * 256;
            int r = idx >> 6, d = idx & 63;
            KV[r*GP + d] = V[base + (size_t)(s0 + r) * DK + d];
        }
        __syncthreads();

        // O += P . V
#pragma unroll 8
        for (int s = 0; s < 64; s++) {
            float4 pv = *(const float4*)&Ps[s*GP + ty*4];
            float4 vv = *(const float4*)&KV[s*GP + tx*4];
            float a[4] = {pv.x, pv.y, pv.z, pv.w};
            float b[4] = {vv.x, vv.y, vv.z, vv.w};
#pragma unroll
            for (int i = 0; i < 4; i++)
#pragma unroll
                for (int j = 0; j < 4; j++)
                    accO[i][j] = fmaf(a[i], b[j], accO[i][j]);
        }
    }

    // epilogue: normalize, write ctx in [b, s, h, d] (== concat layout)
    const int b = bh >> 4, h = bh & 15;
#pragma unroll
    for (int i = 0; i < 4; i++) {
        float inv = 1.0f / lrow[i];
        int q = q0 + ty*4 + i;
        float4 v = make_float4(accO[i][0]*inv, accO[i][1]*inv,
                               accO[i][2]*inv, accO[i][3]*inv);
        *(float4*)&ctx[((size_t)(b*SEQ + q) * NH + h) * DK + tx*4] = v;
    }
}

// ---------------------------------------------------------------------------
extern "C" void kernel_launch(void* const* d_in, const int* in_sizes, int n_in,
                              void* d_out, int out_size)
{
    const float* Xq = (const float*)d_in[0];
    const float* Xk = (const float*)d_in[1];
    const float* Xv = (const float*)d_in[2];
    const float* Wq = (const float*)d_in[3];
    const float* bq = (const float*)d_in[4];
    const float* Wk = (const float*)d_in[5];
    const float* bk = (const float*)d_in[6];
    const float* Wv = (const float*)d_in[7];
    const float* bv = (const float*)d_in[8];
    const float* Wo = (const float*)d_in[9];
    const float* bo = (const float*)d_in[10];
    float* out = (float*)d_out;

    float *Qp, *Kp, *Vp, *Cp;
    cudaGetSymbolAddress((void**)&Qp, g_Q);
    cudaGetSymbolAddress((void**)&Kp, g_K);
    cudaGetSymbolAddress((void**)&Vp, g_V);
    cudaGetSymbolAddress((void**)&Cp, g_ctx);

    const int attn_smem_bytes = 3 * 64 * GP * (int)sizeof(float);  // 52224
    cudaFuncSetAttribute(attn_kernel,
                         cudaFuncAttributeMaxDynamicSharedMemorySize,
                         attn_smem_bytes);

    dim3 blk(256);
    dim3 gp(DM/64, MROWS/64);        // 16 x 64
    gemm_proj<<<gp, blk>>>(Xq, Wq, bq, Qp, 1);
    gemm_proj<<<gp, blk>>>(Xk, Wk, bk, Kp, 1);
    gemm_proj<<<gp, blk>>>(Xv, Wv, bv, Vp, 1);

    dim3 ga(SEQ/64, BATCH*NH);       // 32 x 32
    attn_kernel<<<ga, blk, attn_smem_bytes>>>(Qp, Kp, Vp, Cp);

    gemm_proj<<<gp, blk>>>(Cp, Wo, bo, out, 0);
}

// round 3
// speedup vs baseline: 1.3865x; 1.3865x over previous
#include <cuda_runtime.h>
#include <cstdint>

#define DM   1024
#define NH   16
#define DK   64
#define BATCH 2
#define SEQ  2048
#define MROWS (BATCH*SEQ)   // 4096
#define GP   68             // smem row pitch (floats) for fp32 gemm kernel

// Scratch (sanctioned __device__ globals; no allocation in kernel_launch)
__device__ float g_Q[BATCH*NH*SEQ*DK];
__device__ float g_K[BATCH*NH*SEQ*DK];
__device__ float g_V[BATCH*NH*SEQ*DK];
__device__ float g_ctx[MROWS*DM];

// ---------------------------------------------------------------------------
// helpers
// ---------------------------------------------------------------------------
__device__ __forceinline__ uint32_t f2tf(float f) {
    uint32_t u;
    asm("cvt.rna.tf32.f32 %0, %1;" : "=r"(u) : "f"(f));
    return u;
}
__device__ __forceinline__ float ex2f(float x) {
    float y;
    asm("ex2.approx.f32 %0, %1;" : "=f"(y) : "f"(x));
    return y;
}
__device__ __forceinline__ void mma_tf32(float* c, const uint32_t* a,
                                         uint32_t b0, uint32_t b1) {
    asm volatile(
        "mma.sync.aligned.m16n8k8.row.col.f32.tf32.tf32.f32 "
        "{%0,%1,%2,%3},{%4,%5,%6,%7},{%8,%9},{%0,%1,%2,%3};"
        : "+f"(c[0]), "+f"(c[1]), "+f"(c[2]), "+f"(c[3])
        : "r"(a[0]), "r"(a[1]), "r"(a[2]), "r"(a[3]), "r"(b0), "r"(b1));
}

// ---------------------------------------------------------------------------
// fp32 SIMT projection GEMM (unchanged from R1 — correctness anchor)
// C[m][n] = sum_k A[m][k] * W[n][k] + bias[n]
// ---------------------------------------------------------------------------
__global__ __launch_bounds__(256)
void gemm_proj(const float* __restrict__ A, const float* __restrict__ W,
               const float* __restrict__ bias, float* __restrict__ C,
               int head_layout)
{
    __shared__ __align__(16) float As[64*GP]; // As[k*GP + m]
    __shared__ __align__(16) float Bs[64*GP]; // Bs[k*GP + n]

    const int m0 = blockIdx.y * 64;
    const int n0 = blockIdx.x * 64;
    const int tid = threadIdx.x;
    const int tx = tid & 15;
    const int ty = tid >> 4;

    float acc[4][4];
#pragma unroll
    for (int i = 0; i < 4; i++)
#pragma unroll
        for (int j = 0; j < 4; j++) acc[i][j] = 0.f;

    for (int kt = 0; kt < DM; kt += 64) {
#pragma unroll
        for (int i = 0; i < 16; i++) {
            int idx = tid + i * 256;
            int r = idx >> 6, k = idx & 63;
            As[k*GP + r] = A[(size_t)(m0 + r) * DM + kt + k];
            Bs[k*GP + r] = W[(size_t)(n0 + r) * DM + kt + k];
        }
        __syncthreads();
#pragma unroll 8
        for (int k = 0; k < 64; k++) {
            float4 av = *(const float4*)&As[k*GP + ty*4];
            float4 bv = *(const float4*)&Bs[k*GP + tx*4];
            float a[4] = {av.x, av.y, av.z, av.w};
            float b[4] = {bv.x, bv.y, bv.z, bv.w};
#pragma unroll
            for (int i = 0; i < 4; i++)
#pragma unroll
                for (int j = 0; j < 4; j++)
                    acc[i][j] = fmaf(a[i], b[j], acc[i][j]);
        }
        __syncthreads();
    }

#pragma unroll
    for (int i = 0; i < 4; i++) {
        int m = m0 + ty*4 + i;
        float4 v;
        v.x = acc[i][0] + bias[n0 + tx*4 + 0];
        v.y = acc[i][1] + bias[n0 + tx*4 + 1];
        v.z = acc[i][2] + bias[n0 + tx*4 + 2];
        v.w = acc[i][3] + bias[n0 + tx*4 + 3];
        if (head_layout) {
            int h = n0 >> 6;
            int b = m >> 11;
            int s = m & (SEQ - 1);
            *(float4*)&C[(((size_t)(b*NH + h) * SEQ + s) * DK) + tx*4] = v;
        } else {
            *(float4*)&C[(size_t)m * DM + n0 + tx*4] = v;
        }
    }
}

// ---------------------------------------------------------------------------
// Flash attention on mma.sync tf32 (m16n8k8).
// Block: 128 q-rows of one (b,h); 8 warps, warp w owns rows w*16..w*16+15.
// kv tile = 64. Q frags held in registers. Softmax in log2 domain.
// smem pitches: Qs/Ps/Ks = 68 (bank 4g+tg conflict-free), Vs = 72 (8tg+g).
// Ps aliases Qs (Q memory dead after frag load); each warp reads only its
// own P rows -> no sync around the P roundtrip.
// ---------------------------------------------------------------------------
#define QS_W (128*68)
#define KS_W (64*68)
#define VS_W (64*72)
#define ATTN_SMEM_BYTES ((QS_W + KS_W + VS_W) * 4)   // 70656

__global__ __launch_bounds__(256)
void attn_mma(const float* __restrict__ Q, const float* __restrict__ K,
              const float* __restrict__ V, float* __restrict__ ctx)
{
    extern __shared__ uint32_t sm[];
    uint32_t* Qs = sm;                 // [128][68], aliased by Ps
    uint32_t* Ps = sm;
    uint32_t* Ks = sm + QS_W;          // [64][68]
    uint32_t* Vs = sm + QS_W + KS_W;   // [64][72]

    const int bh = blockIdx.y;
    const int q0 = blockIdx.x * 128;
    const size_t base = (size_t)bh * SEQ * DK;
    const int tid = threadIdx.x;
    const int w = tid >> 5;
    const int lane = tid & 31;
    const int g = lane >> 2, tg = lane & 3;
    const float QSCALE = 0.125f * 1.4426950408889634f;  // 1/sqrt(dk) * log2(e)

    // stage Q (scaled into log2 domain, tf32)
#pragma unroll
    for (int i = 0; i < 8; i++) {
        int f = tid + i * 256;
        int r = f >> 4, kq = (f & 15) * 4;
        float4 v = *(const float4*)&Q[base + (size_t)(q0 + r) * DK + kq];
        uint4 u;
        u.x = f2tf(v.x * QSCALE); u.y = f2tf(v.y * QSCALE);
        u.z = f2tf(v.z * QSCALE); u.w = f2tf(v.w * QSCALE);
        *(uint4*)&Qs[r*68 + kq] = u;
    }
    __syncthreads();

    // Q fragments -> registers (A operand, m16 rows = warp's own rows)
    uint32_t qf[8][4];
    const int pr0 = (w*16 + g) * 68;
    const int pr1 = pr0 + 8 * 68;
#pragma unroll
    for (int kt = 0; kt < 8; kt++) {
        int c = kt*8 + tg;
        qf[kt][0] = Qs[pr0 + c];
        qf[kt][1] = Qs[pr1 + c];
        qf[kt][2] = Qs[pr0 + c + 4];
        qf[kt][3] = Qs[pr1 + c + 4];
    }

    float of[8][4];
#pragma unroll
    for (int dt = 0; dt < 8; dt++)
#pragma unroll
        for (int j = 0; j < 4; j++) of[dt][j] = 0.f;
    float m0 = -1e30f, m1 = -1e30f, l0 = 0.f, l1 = 0.f;

    for (int s0 = 0; s0 < SEQ; s0 += 64) {
        // stage K and V tiles (tf32)
#pragma unroll
        for (int i = 0; i < 4; i++) {
            int f = tid + i * 256;
            int r = f >> 4, kq = (f & 15) * 4;
            float4 kv = *(const float4*)&K[base + (size_t)(s0 + r) * DK + kq];
            uint4 uk;
            uk.x = f2tf(kv.x); uk.y = f2tf(kv.y);
            uk.z = f2tf(kv.z); uk.w = f2tf(kv.w);
            *(uint4*)&Ks[r*68 + kq] = uk;
            float4 vv = *(const float4*)&V[base + (size_t)(s0 + r) * DK + kq];
            uint4 uv;
            uv.x = f2tf(vv.x); uv.y = f2tf(vv.y);
            uv.z = f2tf(vv.z); uv.w = f2tf(vv.w);
            *(uint4*)&Vs[r*72 + kq] = uv;
        }
        __syncthreads();

        // S = Q . K^T  (warp: m16 x n64, k=64)
        float sacc[8][4];
#pragma unroll
        for (int nt = 0; nt < 8; nt++)
#pragma unroll
            for (int j = 0; j < 4; j++) sacc[nt][j] = 0.f;
#pragma unroll
        for (int kt = 0; kt < 8; kt++) {
#pragma unroll
            for (int nt = 0; nt < 8; nt++) {
                int ka = (nt*8 + g)*68 + kt*8 + tg;
                mma_tf32(sacc[nt], qf[kt], Ks[ka], Ks[ka + 4]);
            }
        }

        // online softmax (rows g and g+8; reduce over tg lanes)
        float tm0 = -1e30f, tm1 = -1e30f;
#pragma unroll
        for (int nt = 0; nt < 8; nt++) {
            tm0 = fmaxf(tm0, fmaxf(sacc[nt][0], sacc[nt][1]));
            tm1 = fmaxf(tm1, fmaxf(sacc[nt][2], sacc[nt][3]));
        }
        tm0 = fmaxf(tm0, __shfl_xor_sync(0xffffffffu, tm0, 1));
        tm0 = fmaxf(tm0, __shfl_xor_sync(0xffffffffu, tm0, 2));
        tm1 = fmaxf(tm1, __shfl_xor_sync(0xffffffffu, tm1, 1));
        tm1 = fmaxf(tm1, __shfl_xor_sync(0xffffffffu, tm1, 2));

        float mn0 = fmaxf(m0, tm0), mn1 = fmaxf(m1, tm1);
        float a0 = ex2f(m0 - mn0), a1 = ex2f(m1 - mn1);
        m0 = mn0; m1 = mn1;

        float rs0 = 0.f, rs1 = 0.f;
#pragma unroll
        for (int nt = 0; nt < 8; nt++) {
            float p0 = ex2f(sacc[nt][0] - mn0);
            float p1 = ex2f(sacc[nt][1] - mn0);
            float p2 = ex2f(sacc[nt][2] - mn1);
            float p3 = ex2f(sacc[nt][3] - mn1);
            sacc[nt][0] = p0; sacc[nt][1] = p1;
            sacc[nt][2] = p2; sacc[nt][3] = p3;
            rs0 += p0 + p1;
            rs1 += p2 + p3;
        }
        rs0 += __shfl_xor_sync(0xffffffffu, rs0, 1);
        rs0 += __shfl_xor_sync(0xffffffffu, rs0, 2);
        rs1 += __shfl_xor_sync(0xffffffffu, rs1, 1);
        rs1 += __shfl_xor_sync(0xffffffffu, rs1, 2);
        l0 = l0 * a0 + rs0;
        l1 = l1 * a1 + rs1;
#pragma unroll
        for (int dt = 0; dt < 8; dt++) {
            of[dt][0] *= a0; of[dt][1] *= a0;
            of[dt][2] *= a1; of[dt][3] *= a1;
        }

        // write P (tf32) to smem — own rows only, no sync needed
#pragma unroll
        for (int nt = 0; nt < 8; nt++) {
            int c = nt*8 + 2*tg;
            Ps[pr0 + c]     = f2tf(sacc[nt][0]);
            Ps[pr0 + c + 1] = f2tf(sacc[nt][1]);
            Ps[pr1 + c]     = f2tf(sacc[nt][2]);
            Ps[pr1 + c + 1] = f2tf(sacc[nt][3]);
        }

        // O += P . V  (warp: m16 x d64, k=64)
#pragma unroll
        for (int kt = 0; kt < 8; kt++) {
            uint32_t pa[4];
            int c = kt*8 + tg;
            pa[0] = Ps[pr0 + c];
            pa[1] = Ps[pr1 + c];
            pa[2] = Ps[pr0 + c + 4];
            pa[3] = Ps[pr1 + c + 4];
            int vr0 = (kt*8 + tg)*72;
            int vr1 = (kt*8 + tg + 4)*72;
#pragma unroll
            for (int dt = 0; dt < 8; dt++) {
                mma_tf32(of[dt], pa, Vs[vr0 + dt*8 + g], Vs[vr1 + dt*8 + g]);
            }
        }
        __syncthreads();   // Ks/Vs consumed before next staging
    }

    // epilogue: normalize, write ctx in [b, s, h, d] concat layout
    float inv0 = 1.0f / l0, inv1 = 1.0f / l1;
    const int b = bh >> 4, h = bh & 15;
    const int sg0 = q0 + w*16 + g, sg1 = sg0 + 8;
#pragma unroll
    for (int dt = 0; dt < 8; dt++) {
        int d = dt*8 + 2*tg;
        float2 v0 = make_float2(of[dt][0]*inv0, of[dt][1]*inv0);
        float2 v1 = make_float2(of[dt][2]*inv1, of[dt][3]*inv1);
        *(float2*)&ctx[((size_t)(b*SEQ + sg0) * NH + h) * DK + d] = v0;
        *(float2*)&ctx[((size_t)(b*SEQ + sg1) * NH + h) * DK + d] = v1;
    }
}

// ---------------------------------------------------------------------------
extern "C" void kernel_launch(void* const* d_in, const int* in_sizes, int n_in,
                              void* d_out, int out_size)
{
    const float* Xq = (const float*)d_in[0];
    const float* Xk = (const float*)d_in[1];
    const float* Xv = (const float*)d_in[2];
    const float* Wq = (const float*)d_in[3];
    const float* bq = (const float*)d_in[4];
    const float* Wk = (const float*)d_in[5];
    const float* bk = (const float*)d_in[6];
    const float* Wv = (const float*)d_in[7];
    const float* bv = (const float*)d_in[8];
    const float* Wo = (const float*)d_in[9];
    const float* bo = (const float*)d_in[10];
    float* out = (float*)d_out;

    float *Qp, *Kp, *Vp, *Cp;
    cudaGetSymbolAddress((void**)&Qp, g_Q);
    cudaGetSymbolAddress((void**)&Kp, g_K);
    cudaGetSymbolAddress((void**)&Vp, g_V);
    cudaGetSymbolAddress((void**)&Cp, g_ctx);

    cudaFuncSetAttribute(attn_mma,
                         cudaFuncAttributeMaxDynamicSharedMemorySize,
                         ATTN_SMEM_BYTES);

    dim3 blk(256);
    dim3 gp(DM/64, MROWS/64);        // 16 x 64
    gemm_proj<<<gp, blk>>>(Xq, Wq, bq, Qp, 1);
    gemm_proj<<<gp, blk>>>(Xk, Wk, bk, Kp, 1);
    gemm_proj<<<gp, blk>>>(Xv, Wv, bv, Vp, 1);

    dim3 ga(SEQ/128, BATCH*NH);      // 16 x 32
    attn_mma<<<ga, blk, ATTN_SMEM_BYTES>>>(Qp, Kp, Vp, Cp);

    gemm_proj<<<gp, blk>>>(Cp, Wo, bo, out, 0);
}

// round 4
// speedup vs baseline: 2.7171x; 1.9596x over previous
#include <cuda_runtime.h>
#include <cstdint>

#define DM   1024
#define NH   16
#define DK   64
#define BATCH 2
#define SEQ  2048
#define MROWS (BATCH*SEQ)   // 4096

// Scratch (sanctioned __device__ globals; no allocation in kernel_launch)
__device__ float g_Q[BATCH*NH*SEQ*DK];
__device__ float g_K[BATCH*NH*SEQ*DK];
__device__ float g_V[BATCH*NH*SEQ*DK];
__device__ float g_ctx[MROWS*DM];

// ---------------------------------------------------------------------------
// helpers
// ---------------------------------------------------------------------------
__device__ __forceinline__ uint32_t f2tf(float f) {
    uint32_t u;
    asm("cvt.rna.tf32.f32 %0, %1;" : "=r"(u) : "f"(f));
    return u;
}
__device__ __forceinline__ float ex2f(float x) {
    float y;
    asm("ex2.approx.f32 %0, %1;" : "=f"(y) : "f"(x));
    return y;
}
__device__ __forceinline__ void mma_tf32(float* c, const uint32_t* a,
                                         uint32_t b0, uint32_t b1) {
    asm volatile(
        "mma.sync.aligned.m16n8k8.row.col.f32.tf32.tf32.f32 "
        "{%0,%1,%2,%3},{%4,%5,%6,%7},{%8,%9},{%0,%1,%2,%3};"
        : "+f"(c[0]), "+f"(c[1]), "+f"(c[2]), "+f"(c[3])
        : "r"(a[0]), "r"(a[1]), "r"(a[2]), "r"(a[3]), "r"(b0), "r"(b1));
}

// ---------------------------------------------------------------------------
// Projection GEMM on mma.sync tf32 with one-sided precision split.
// C[m][n] = sum_k A[m][k] * W[n][k] + bias[n]
//   W staged as Whi + Wlo (tf32 split) -> W error eliminated; A single tf32.
// Block tile 128m x 64n, K-chunk 64. 8 warps as 4m x 2n -> warp tile 32x32.
// smem pitch 68 (conflict-free for (r*68 + 8*kt + tg) fragment pattern).
// head_layout=1: n-tile == head; write to [b,h,s,d] scratch.
// ---------------------------------------------------------------------------
#define GEMM_SMEM_WORDS (256*68)          // As 128*68 + Wh 64*68 + Wl 64*68
#define GEMM_SMEM_BYTES (GEMM_SMEM_WORDS*4)  // 69632

__global__ __launch_bounds__(256, 2)
void gemm_mma(const float* __restrict__ A, const float* __restrict__ W,
              const float* __restrict__ bias, float* __restrict__ C,
              int head_layout)
{
    extern __shared__ uint32_t gsm[];
    uint32_t* As = gsm;                // [128][68]
    uint32_t* Wh = gsm + 128*68;       // [64][68]
    uint32_t* Wl = gsm + 192*68;       // [64][68]

    const int m0 = blockIdx.y * 128;
    const int n0 = blockIdx.x * 64;
    const int tid = threadIdx.x;
    const int w = tid >> 5;
    const int lane = tid & 31;
    const int g = lane >> 2, tg = lane & 3;
    const int wm = w & 3;              // m group (32 rows)
    const int wn = w >> 2;             // n group (32 cols)

    float acc[2][4][4];
#pragma unroll
    for (int mi = 0; mi < 2; mi++)
#pragma unroll
        for (int nt = 0; nt < 4; nt++)
#pragma unroll
            for (int j = 0; j < 4; j++) acc[mi][nt][j] = 0.f;

    for (int kt = 0; kt < DM; kt += 64) {
        __syncthreads();   // previous chunk's mma reads complete

        // stage A tile 128x64 (tf32), 8 float4 per thread
#pragma unroll
        for (int i = 0; i < 8; i++) {
            int f = tid + i * 256;
            int r = f >> 4, c = (f & 15) * 4;
            float4 v = *(const float4*)&A[(size_t)(m0 + r) * DM + kt + c];
            uint4 u;
            u.x = f2tf(v.x); u.y = f2tf(v.y);
            u.z = f2tf(v.z); u.w = f2tf(v.w);
            *(uint4*)&As[r*68 + c] = u;
        }
        // stage W tile 64x64 split hi/lo, 4 float4 per thread
#pragma unroll
        for (int i = 0; i < 4; i++) {
            int f = tid + i * 256;
            int r = f >> 4, c = (f & 15) * 4;
            float4 v = *(const float4*)&W[(size_t)(n0 + r) * DM + kt + c];
            uint4 uh, ul;
            uh.x = f2tf(v.x); uh.y = f2tf(v.y);
            uh.z = f2tf(v.z); uh.w = f2tf(v.w);
            ul.x = f2tf(v.x - __uint_as_float(uh.x));
            ul.y = f2tf(v.y - __uint_as_float(uh.y));
            ul.z = f2tf(v.z - __uint_as_float(uh.z));
            ul.w = f2tf(v.w - __uint_as_float(uh.w));
            *(uint4*)&Wh[r*68 + c] = uh;
            *(uint4*)&Wl[r*68 + c] = ul;
        }
        __syncthreads();

#pragma unroll
        for (int k8 = 0; k8 < 8; k8++) {
            uint32_t af[2][4];
#pragma unroll
            for (int mi = 0; mi < 2; mi++) {
                int ar = (wm*32 + mi*16 + g)*68 + k8*8 + tg;
                af[mi][0] = As[ar];
                af[mi][1] = As[ar + 8*68];
                af[mi][2] = As[ar + 4];
                af[mi][3] = As[ar + 8*68 + 4];
            }
#pragma unroll
            for (int nt = 0; nt < 4; nt++) {
                int ka = (wn*32 + nt*8 + g)*68 + k8*8 + tg;
                uint32_t bh0 = Wh[ka], bh1 = Wh[ka + 4];
                uint32_t bl0 = Wl[ka], bl1 = Wl[ka + 4];
#pragma unroll
                for (int mi = 0; mi < 2; mi++) {
                    mma_tf32(acc[mi][nt], af[mi], bh0, bh1);
                    mma_tf32(acc[mi][nt], af[mi], bl0, bl1);
                }
            }
        }
    }

    // epilogue: bias + store (float2 per fragment row)
    const int h = blockIdx.x;   // n-tile == head when head_layout
#pragma unroll
    for (int nt = 0; nt < 4; nt++) {
        int nc = wn*32 + nt*8 + 2*tg;           // col within 64-wide tile
        float b0 = bias[n0 + nc], b1 = bias[n0 + nc + 1];
#pragma unroll
        for (int mi = 0; mi < 2; mi++) {
            int mA = m0 + wm*32 + mi*16 + g;
            int mB = mA + 8;
            float2 vA = make_float2(acc[mi][nt][0] + b0, acc[mi][nt][1] + b1);
            float2 vB = make_float2(acc[mi][nt][2] + b0, acc[mi][nt][3] + b1);
            if (head_layout) {
                int bA = mA >> 11, sA = mA & (SEQ-1);
                int bB = mB >> 11, sB = mB & (SEQ-1);
                *(float2*)&C[(((size_t)(bA*NH + h) * SEQ + sA) * DK) + nc] = vA;
                *(float2*)&C[(((size_t)(bB*NH + h) * SEQ + sB) * DK) + nc] = vB;
            } else {
                *(float2*)&C[(size_t)mA * DM + n0 + nc] = vA;
                *(float2*)&C[(size_t)mB * DM + n0 + nc] = vB;
            }
        }
    }
}

// ---------------------------------------------------------------------------
// Flash attention on mma.sync tf32 (unchanged from R2).
// ---------------------------------------------------------------------------
#define QS_W (128*68)
#define KS_W (64*68)
#define VS_W (64*72)
#define ATTN_SMEM_BYTES ((QS_W + KS_W + VS_W) * 4)   // 70656

__global__ __launch_bounds__(256)
void attn_mma(const float* __restrict__ Q, const float* __restrict__ K,
              const float* __restrict__ V, float* __restrict__ ctx)
{
    extern __shared__ uint32_t sm[];
    uint32_t* Qs = sm;                 // [128][68], aliased by Ps
    uint32_t* Ps = sm;
    uint32_t* Ks = sm + QS_W;          // [64][68]
    uint32_t* Vs = sm + QS_W + KS_W;   // [64][72]

    const int bh = blockIdx.y;
    const int q0 = blockIdx.x * 128;
    const size_t base = (size_t)bh * SEQ * DK;
    const int tid = threadIdx.x;
    const int w = tid >> 5;
    const int lane = tid & 31;
    const int g = lane >> 2, tg = lane & 3;
    const float QSCALE = 0.125f * 1.4426950408889634f;  // 1/sqrt(dk) * log2(e)

#pragma unroll
    for (int i = 0; i < 8; i++) {
        int f = tid + i * 256;
        int r = f >> 4, kq = (f & 15) * 4;
        float4 v = *(const float4*)&Q[base + (size_t)(q0 + r) * DK + kq];
        uint4 u;
        u.x = f2tf(v.x * QSCALE); u.y = f2tf(v.y * QSCALE);
        u.z = f2tf(v.z * QSCALE); u.w = f2tf(v.w * QSCALE);
        *(uint4*)&Qs[r*68 + kq] = u;
    }
    __syncthreads();

    uint32_t qf[8][4];
    const int pr0 = (w*16 + g) * 68;
    const int pr1 = pr0 + 8 * 68;
#pragma unroll
    for (int kt = 0; kt < 8; kt++) {
        int c = kt*8 + tg;
        qf[kt][0] = Qs[pr0 + c];
        qf[kt][1] = Qs[pr1 + c];
        qf[kt][2] = Qs[pr0 + c + 4];
        qf[kt][3] = Qs[pr1 + c + 4];
    }

    float of[8][4];
#pragma unroll
    for (int dt = 0; dt < 8; dt++)
#pragma unroll
        for (int j = 0; j < 4; j++) of[dt][j] = 0.f;
    float m0 = -1e30f, m1 = -1e30f, l0 = 0.f, l1 = 0.f;

    for (int s0 = 0; s0 < SEQ; s0 += 64) {
#pragma unroll
        for (int i = 0; i < 4; i++) {
            int f = tid + i * 256;
            int r = f >> 4, kq = (f & 15) * 4;
            float4 kv = *(const float4*)&K[base + (size_t)(s0 + r) * DK + kq];
            uint4 uk;
            uk.x = f2tf(kv.x); uk.y = f2tf(kv.y);
            uk.z = f2tf(kv.z); uk.w = f2tf(kv.w);
            *(uint4*)&Ks[r*68 + kq] = uk;
            float4 vv = *(const float4*)&V[base + (size_t)(s0 + r) * DK + kq];
            uint4 uv;
            uv.x = f2tf(vv.x); uv.y = f2tf(vv.y);
            uv.z = f2tf(vv.z); uv.w = f2tf(vv.w);
            *(uint4*)&Vs[r*72 + kq] = uv;
        }
        __syncthreads();

        float sacc[8][4];
#pragma unroll
        for (int nt = 0; nt < 8; nt++)
#pragma unroll
            for (int j = 0; j < 4; j++) sacc[nt][j] = 0.f;
#pragma unroll
        for (int kt = 0; kt < 8; kt++) {
#pragma unroll
            for (int nt = 0; nt < 8; nt++) {
                int ka = (nt*8 + g)*68 + kt*8 + tg;
                mma_tf32(sacc[nt], qf[kt], Ks[ka], Ks[ka + 4]);
            }
        }

        float tm0 = -1e30f, tm1 = -1e30f;
#pragma unroll
        for (int nt = 0; nt < 8; nt++) {
            tm0 = fmaxf(tm0, fmaxf(sacc[nt][0], sacc[nt][1]));
            tm1 = fmaxf(tm1, fmaxf(sacc[nt][2], sacc[nt][3]));
        }
        tm0 = fmaxf(tm0, __shfl_xor_sync(0xffffffffu, tm0, 1));
        tm0 = fmaxf(tm0, __shfl_xor_sync(0xffffffffu, tm0, 2));
        tm1 = fmaxf(tm1, __shfl_xor_sync(0xffffffffu, tm1, 1));
        tm1 = fmaxf(tm1, __shfl_xor_sync(0xffffffffu, tm1, 2));

        float mn0 = fmaxf(m0, tm0), mn1 = fmaxf(m1, tm1);
        float a0 = ex2f(m0 - mn0), a1 = ex2f(m1 - mn1);
        m0 = mn0; m1 = mn1;

        float rs0 = 0.f, rs1 = 0.f;
#pragma unroll
        for (int nt = 0; nt < 8; nt++) {
            float p0 = ex2f(sacc[nt][0] - mn0);
            float p1 = ex2f(sacc[nt][1] - mn0);
            float p2 = ex2f(sacc[nt][2] - mn1);
            float p3 = ex2f(sacc[nt][3] - mn1);
            sacc[nt][0] = p0; sacc[nt][1] = p1;
            sacc[nt][2] = p2; sacc[nt][3] = p3;
            rs0 += p0 + p1;
            rs1 += p2 + p3;
        }
        rs0 += __shfl_xor_sync(0xffffffffu, rs0, 1);
        rs0 += __shfl_xor_sync(0xffffffffu, rs0, 2);
        rs1 += __shfl_xor_sync(0xffffffffu, rs1, 1);
        rs1 += __shfl_xor_sync(0xffffffffu, rs1, 2);
        l0 = l0 * a0 + rs0;
        l1 = l1 * a1 + rs1;
#pragma unroll
        for (int dt = 0; dt < 8; dt++) {
            of[dt][0] *= a0; of[dt][1] *= a0;
            of[dt][2] *= a1; of[dt][3] *= a1;
        }

#pragma unroll
        for (int nt = 0; nt < 8; nt++) {
            int c = nt*8 + 2*tg;
            Ps[pr0 + c]     = f2tf(sacc[nt][0]);
            Ps[pr0 + c + 1] = f2tf(sacc[nt][1]);
            Ps[pr1 + c]     = f2tf(sacc[nt][2]);
            Ps[pr1 + c + 1] = f2tf(sacc[nt][3]);
        }

#pragma unroll
        for (int kt = 0; kt < 8; kt++) {
            uint32_t pa[4];
            int c = kt*8 + tg;
            pa[0] = Ps[pr0 + c];
            pa[1] = Ps[pr1 + c];
            pa[2] = Ps[pr0 + c + 4];
            pa[3] = Ps[pr1 + c + 4];
            int vr0 = (kt*8 + tg)*72;
            int vr1 = (kt*8 + tg + 4)*72;
#pragma unroll
            for (int dt = 0; dt < 8; dt++) {
                mma_tf32(of[dt], pa, Vs[vr0 + dt*8 + g], Vs[vr1 + dt*8 + g]);
            }
        }
        __syncthreads();
    }

    float inv0 = 1.0f / l0, inv1 = 1.0f / l1;
    const int b = bh >> 4, h = bh & 15;
    const int sg0 = q0 + w*16 + g, sg1 = sg0 + 8;
#pragma unroll
    for (int dt = 0; dt < 8; dt++) {
        int d = dt*8 + 2*tg;
        float2 v0 = make_float2(of[dt][0]*inv0, of[dt][1]*inv0);
        float2 v1 = make_float2(of[dt][2]*inv1, of[dt][3]*inv1);
        *(float2*)&ctx[((size_t)(b*SEQ + sg0) * NH + h) * DK + d] = v0;
        *(float2*)&ctx[((size_t)(b*SEQ + sg1) * NH + h) * DK + d] = v1;
    }
}

// ---------------------------------------------------------------------------
extern "C" void kernel_launch(void* const* d_in, const int* in_sizes, int n_in,
                              void* d_out, int out_size)
{
    const float* Xq = (const float*)d_in[0];
    const float* Xk = (const float*)d_in[1];
    const float* Xv = (const float*)d_in[2];
    const float* Wq = (const float*)d_in[3];
    const float* bq = (const float*)d_in[4];
    const float* Wk = (const float*)d_in[5];
    const float* bk = (const float*)d_in[6];
    const float* Wv = (const float*)d_in[7];
    const float* bv = (const float*)d_in[8];
    const float* Wo = (const float*)d_in[9];
    const float* bo = (const float*)d_in[10];
    float* out = (float*)d_out;

    float *Qp, *Kp, *Vp, *Cp;
    cudaGetSymbolAddress((void**)&Qp, g_Q);
    cudaGetSymbolAddress((void**)&Kp, g_K);
    cudaGetSymbolAddress((void**)&Vp, g_V);
    cudaGetSymbolAddress((void**)&Cp, g_ctx);

    cudaFuncSetAttribute(gemm_mma,
                         cudaFuncAttributeMaxDynamicSharedMemorySize,
                         GEMM_SMEM_BYTES);
    cudaFuncSetAttribute(attn_mma,
                         cudaFuncAttributeMaxDynamicSharedMemorySize,
                         ATTN_SMEM_BYTES);

    dim3 blk(256);
    dim3 gp(DM/64, MROWS/128);       // 16 x 32 = 512 blocks
    gemm_mma<<<gp, blk, GEMM_SMEM_BYTES>>>(Xq, Wq, bq, Qp, 1);
    gemm_mma<<<gp, blk, GEMM_SMEM_BYTES>>>(Xk, Wk, bk, Kp, 1);
    gemm_mma<<<gp, blk, GEMM_SMEM_BYTES>>>(Xv, Wv, bv, Vp, 1);

    dim3 ga(SEQ/128, BATCH*NH);      // 16 x 32
    attn_mma<<<ga, blk, ATTN_SMEM_BYTES>>>(Qp, Kp, Vp, Cp);

    gemm_mma<<<gp, blk, GEMM_SMEM_BYTES>>>(Cp, Wo, bo, out, 0);
}

// round 5
// speedup vs baseline: 3.0769x; 1.1324x over previous
#include <cuda_runtime.h>
#include <cstdint>

#define DM   1024
#define NH   16
#define DK   64
#define BATCH 2
#define SEQ  2048
#define MROWS (BATCH*SEQ)   // 4096

// Scratch (sanctioned __device__ globals; no allocation in kernel_launch)
__device__ float g_Q[BATCH*NH*SEQ*DK];
__device__ float g_K[BATCH*NH*SEQ*DK];
__device__ float g_V[BATCH*NH*SEQ*DK];
__device__ float g_ctx[MROWS*DM];

// ---------------------------------------------------------------------------
// helpers
// ---------------------------------------------------------------------------
__device__ __forceinline__ uint32_t f2tf(float f) {
    uint32_t u;
    asm("cvt.rna.tf32.f32 %0, %1;" : "=r"(u) : "f"(f));
    return u;
}
__device__ __forceinline__ float ex2f(float x) {
    float y;
    asm("ex2.approx.f32 %0, %1;" : "=f"(y) : "f"(x));
    return y;
}
__device__ __forceinline__ void mma_tf32(float* c, const uint32_t* a,
                                         uint32_t b0, uint32_t b1) {
    asm volatile(
        "mma.sync.aligned.m16n8k8.row.col.f32.tf32.tf32.f32 "
        "{%0,%1,%2,%3},{%4,%5,%6,%7},{%8,%9},{%0,%1,%2,%3};"
        : "+f"(c[0]), "+f"(c[1]), "+f"(c[2]), "+f"(c[3])
        : "r"(a[0]), "r"(a[1]), "r"(a[2]), "r"(a[3]), "r"(b0), "r"(b1));
}

// ---------------------------------------------------------------------------
// Projection GEMM on mma.sync tf32 with one-sided precision split (W = hi+lo).
// Block tile 128m x 64n, K-chunk 64; 8 warps as 4m x 2n (warp tile 32x32).
// qkv_mode=1: kernel handles Q/K/V via blockIdx.z (fused launch, head layout).
// qkv_mode=0: single output projection (row-major out).
// ---------------------------------------------------------------------------
#define GEMM_SMEM_WORDS (256*68)          // As 128*68 + Wh 64*68 + Wl 64*68
#define GEMM_SMEM_BYTES (GEMM_SMEM_WORDS*4)  // 69632

__global__ __launch_bounds__(256, 2)
void gemm_mma(const float* __restrict__ A0, const float* __restrict__ A1,
              const float* __restrict__ A2,
              const float* __restrict__ W0, const float* __restrict__ W1,
              const float* __restrict__ W2,
              const float* __restrict__ b0p, const float* __restrict__ b1p,
              const float* __restrict__ b2p,
              float* __restrict__ C0, float* __restrict__ C1,
              float* __restrict__ C2,
              int qkv_mode)
{
    extern __shared__ uint32_t gsm[];
    uint32_t* As = gsm;                // [128][68]
    uint32_t* Wh = gsm + 128*68;       // [64][68]
    uint32_t* Wl = gsm + 192*68;       // [64][68]

    const int z = blockIdx.z;
    const float* A    = (z == 0) ? A0 : (z == 1) ? A1 : A2;
    const float* W    = (z == 0) ? W0 : (z == 1) ? W1 : W2;
    const float* bias = (z == 0) ? b0p : (z == 1) ? b1p : b2p;
    float*       C    = (z == 0) ? C0 : (z == 1) ? C1 : C2;

    const int m0 = blockIdx.y * 128;
    const int n0 = blockIdx.x * 64;
    const int tid = threadIdx.x;
    const int w = tid >> 5;
    const int lane = tid & 31;
    const int g = lane >> 2, tg = lane & 3;
    const int wm = w & 3;              // m group (32 rows)
    const int wn = w >> 2;             // n group (32 cols)

    float acc[2][4][4];
#pragma unroll
    for (int mi = 0; mi < 2; mi++)
#pragma unroll
        for (int nt = 0; nt < 4; nt++)
#pragma unroll
            for (int j = 0; j < 4; j++) acc[mi][nt][j] = 0.f;

    for (int kt = 0; kt < DM; kt += 64) {
        __syncthreads();

#pragma unroll
        for (int i = 0; i < 8; i++) {
            int f = tid + i * 256;
            int r = f >> 4, c = (f & 15) * 4;
            float4 v = *(const float4*)&A[(size_t)(m0 + r) * DM + kt + c];
            uint4 u;
            u.x = f2tf(v.x); u.y = f2tf(v.y);
            u.z = f2tf(v.z); u.w = f2tf(v.w);
            *(uint4*)&As[r*68 + c] = u;
        }
#pragma unroll
        for (int i = 0; i < 4; i++) {
            int f = tid + i * 256;
            int r = f >> 4, c = (f & 15) * 4;
            float4 v = *(const float4*)&W[(size_t)(n0 + r) * DM + kt + c];
            uint4 uh, ul;
            uh.x = f2tf(v.x); uh.y = f2tf(v.y);
            uh.z = f2tf(v.z); uh.w = f2tf(v.w);
            ul.x = f2tf(v.x - __uint_as_float(uh.x));
            ul.y = f2tf(v.y - __uint_as_float(uh.y));
            ul.z = f2tf(v.z - __uint_as_float(uh.z));
            ul.w = f2tf(v.w - __uint_as_float(uh.w));
            *(uint4*)&Wh[r*68 + c] = uh;
            *(uint4*)&Wl[r*68 + c] = ul;
        }
        __syncthreads();

#pragma unroll
        for (int k8 = 0; k8 < 8; k8++) {
            uint32_t af[2][4];
#pragma unroll
            for (int mi = 0; mi < 2; mi++) {
                int ar = (wm*32 + mi*16 + g)*68 + k8*8 + tg;
                af[mi][0] = As[ar];
                af[mi][1] = As[ar + 8*68];
                af[mi][2] = As[ar + 4];
                af[mi][3] = As[ar + 8*68 + 4];
            }
#pragma unroll
            for (int nt = 0; nt < 4; nt++) {
                int ka = (wn*32 + nt*8 + g)*68 + k8*8 + tg;
                uint32_t bh0 = Wh[ka], bh1 = Wh[ka + 4];
                uint32_t bl0 = Wl[ka], bl1 = Wl[ka + 4];
#pragma unroll
                for (int mi = 0; mi < 2; mi++) {
                    mma_tf32(acc[mi][nt], af[mi], bh0, bh1);
                    mma_tf32(acc[mi][nt], af[mi], bl0, bl1);
                }
            }
        }
    }

    const int h = blockIdx.x;
#pragma unroll
    for (int nt = 0; nt < 4; nt++) {
        int nc = wn*32 + nt*8 + 2*tg;
        float bb0 = bias[n0 + nc], bb1 = bias[n0 + nc + 1];
#pragma unroll
        for (int mi = 0; mi < 2; mi++) {
            int mA = m0 + wm*32 + mi*16 + g;
            int mB = mA + 8;
            float2 vA = make_float2(acc[mi][nt][0] + bb0, acc[mi][nt][1] + bb1);
            float2 vB = make_float2(acc[mi][nt][2] + bb0, acc[mi][nt][3] + bb1);
            if (qkv_mode) {
                int bA = mA >> 11, sA = mA & (SEQ-1);
                int bB = mB >> 11, sB = mB & (SEQ-1);
                *(float2*)&C[(((size_t)(bA*NH + h) * SEQ + sA) * DK) + nc] = vA;
                *(float2*)&C[(((size_t)(bB*NH + h) * SEQ + sB) * DK) + nc] = vB;
            } else {
                *(float2*)&C[(size_t)mA * DM + n0 + nc] = vA;
                *(float2*)&C[(size_t)mB * DM + n0 + nc] = vB;
            }
        }
    }
}

// ---------------------------------------------------------------------------
// Flash attention on mma.sync tf32, v2: 2 blocks/SM.
// Q stays in smem (A-frags reloaded per k-step, no qf registers);
// P gets its own buffer; launch_bounds(256,2) caps regs at 128.
// smem: Qs 128x68 | Ks 64x68 | Vs 64x72 | Ps 128x68 = 105472 B.
// ---------------------------------------------------------------------------
#define AQ_W (128*68)
#define AK_W (64*68)
#define AV_W (64*72)
#define AP_W (128*68)
#define ATTN_SMEM_BYTES ((AQ_W + AK_W + AV_W + AP_W) * 4)   // 105472

__global__ __launch_bounds__(256, 2)
void attn_mma(const float* __restrict__ Q, const float* __restrict__ K,
              const float* __restrict__ V, float* __restrict__ ctx)
{
    extern __shared__ uint32_t sm[];
    uint32_t* Qs = sm;                        // [128][68]
    uint32_t* Ks = sm + AQ_W;                 // [64][68]
    uint32_t* Vs = sm + AQ_W + AK_W;          // [64][72]
    uint32_t* Ps = sm + AQ_W + AK_W + AV_W;   // [128][68]

    const int bh = blockIdx.y;
    const int q0 = blockIdx.x * 128;
    const size_t base = (size_t)bh * SEQ * DK;
    const int tid = threadIdx.x;
    const int w = tid >> 5;
    const int lane = tid & 31;
    const int g = lane >> 2, tg = lane & 3;
    const float QSCALE = 0.125f * 1.4426950408889634f;  // 1/sqrt(dk) * log2(e)

    // stage Q once (scaled into log2 domain, tf32); persists whole loop
#pragma unroll
    for (int i = 0; i < 8; i++) {
        int f = tid + i * 256;
        int r = f >> 4, kq = (f & 15) * 4;
        float4 v = *(const float4*)&Q[base + (size_t)(q0 + r) * DK + kq];
        uint4 u;
        u.x = f2tf(v.x * QSCALE); u.y = f2tf(v.y * QSCALE);
        u.z = f2tf(v.z * QSCALE); u.w = f2tf(v.w * QSCALE);
        *(uint4*)&Qs[r*68 + kq] = u;
    }

    const int pr0 = (w*16 + g) * 68;    // own-row base (Q/P row for this lane)
    const int pr1 = pr0 + 8 * 68;

    float of[8][4];
#pragma unroll
    for (int dt = 0; dt < 8; dt++)
#pragma unroll
        for (int j = 0; j < 4; j++) of[dt][j] = 0.f;
    float m0 = -1e30f, m1 = -1e30f, l0 = 0.f, l1 = 0.f;

    for (int s0 = 0; s0 < SEQ; s0 += 64) {
        __syncthreads();   // prev tile's mma reads of Ks/Vs done (also fences Q stage)

        // stage K and V tiles (tf32)
#pragma unroll
        for (int i = 0; i < 4; i++) {
            int f = tid + i * 256;
            int r = f >> 4, kq = (f & 15) * 4;
            float4 kv = *(const float4*)&K[base + (size_t)(s0 + r) * DK + kq];
            uint4 uk;
            uk.x = f2tf(kv.x); uk.y = f2tf(kv.y);
            uk.z = f2tf(kv.z); uk.w = f2tf(kv.w);
            *(uint4*)&Ks[r*68 + kq] = uk;
            float4 vv = *(const float4*)&V[base + (size_t)(s0 + r) * DK + kq];
            uint4 uv;
            uv.x = f2tf(vv.x); uv.y = f2tf(vv.y);
            uv.z = f2tf(vv.z); uv.w = f2tf(vv.w);
            *(uint4*)&Vs[r*72 + kq] = uv;
        }
        __syncthreads();

        // S = Q . K^T  (warp: m16 x n64, k=64); Q frags from smem
        float sacc[8][4];
#pragma unroll
        for (int nt = 0; nt < 8; nt++)
#pragma unroll
            for (int j = 0; j < 4; j++) sacc[nt][j] = 0.f;
#pragma unroll
        for (int kt = 0; kt < 8; kt++) {
            uint32_t qf[4];
            int c = kt*8 + tg;
            qf[0] = Qs[pr0 + c];
            qf[1] = Qs[pr1 + c];
            qf[2] = Qs[pr0 + c + 4];
            qf[3] = Qs[pr1 + c + 4];
#pragma unroll
            for (int nt = 0; nt < 8; nt++) {
                int ka = (nt*8 + g)*68 + kt*8 + tg;
                mma_tf32(sacc[nt], qf, Ks[ka], Ks[ka + 4]);
            }
        }

        // online softmax (rows g and g+8; reduce over tg lanes)
        float tm0 = -1e30f, tm1 = -1e30f;
#pragma unroll
        for (int nt = 0; nt < 8; nt++) {
            tm0 = fmaxf(tm0, fmaxf(sacc[nt][0], sacc[nt][1]));
            tm1 = fmaxf(tm1, fmaxf(sacc[nt][2], sacc[nt][3]));
        }
        tm0 = fmaxf(tm0, __shfl_xor_sync(0xffffffffu, tm0, 1));
        tm0 = fmaxf(tm0, __shfl_xor_sync(0xffffffffu, tm0, 2));
        tm1 = fmaxf(tm1, __shfl_xor_sync(0xffffffffu, tm1, 1));
        tm1 = fmaxf(tm1, __shfl_xor_sync(0xffffffffu, tm1, 2));

        float mn0 = fmaxf(m0, tm0), mn1 = fmaxf(m1, tm1);
        float a0 = ex2f(m0 - mn0), a1 = ex2f(m1 - mn1);
        m0 = mn0; m1 = mn1;

        float rs0 = 0.f, rs1 = 0.f;
#pragma unroll
        for (int nt = 0; nt < 8; nt++) {
            float p0 = ex2f(sacc[nt][0] - mn0);
            float p1 = ex2f(sacc[nt][1] - mn0);
            float p2 = ex2f(sacc[nt][2] - mn1);
            float p3 = ex2f(sacc[nt][3] - mn1);
            sacc[nt][0] = p0; sacc[nt][1] = p1;
            sacc[nt][2] = p2; sacc[nt][3] = p3;
            rs0 += p0 + p1;
            rs1 += p2 + p3;
        }
        rs0 += __shfl_xor_sync(0xffffffffu, rs0, 1);
        rs0 += __shfl_xor_sync(0xffffffffu, rs0, 2);
        rs1 += __shfl_xor_sync(0xffffffffu, rs1, 1);
        rs1 += __shfl_xor_sync(0xffffffffu, rs1, 2);
        l0 = l0 * a0 + rs0;
        l1 = l1 * a1 + rs1;
#pragma unroll
        for (int dt = 0; dt < 8; dt++) {
            of[dt][0] *= a0; of[dt][1] *= a0;
            of[dt][2] *= a1; of[dt][3] *= a1;
        }

        // write P (tf32) — own rows only, no sync needed
#pragma unroll
        for (int nt = 0; nt < 8; nt++) {
            int c = nt*8 + 2*tg;
            Ps[pr0 + c]     = f2tf(sacc[nt][0]);
            Ps[pr0 + c + 1] = f2tf(sacc[nt][1]);
            Ps[pr1 + c]     = f2tf(sacc[nt][2]);
            Ps[pr1 + c + 1] = f2tf(sacc[nt][3]);
        }

        // O += P . V  (warp: m16 x d64, k=64)
#pragma unroll
        for (int kt = 0; kt < 8; kt++) {
            uint32_t pa[4];
            int c = kt*8 + tg;
            pa[0] = Ps[pr0 + c];
            pa[1] = Ps[pr1 + c];
            pa[2] = Ps[pr0 + c + 4];
            pa[3] = Ps[pr1 + c + 4];
            int vr0 = (kt*8 + tg)*72;
            int vr1 = (kt*8 + tg + 4)*72;
#pragma unroll
            for (int dt = 0; dt < 8; dt++) {
                mma_tf32(of[dt], pa, Vs[vr0 + dt*8 + g], Vs[vr1 + dt*8 + g]);
            }
        }
    }

    // epilogue: normalize, write ctx in [b, s, h, d] concat layout
    float inv0 = 1.0f / l0, inv1 = 1.0f / l1;
    const int b = bh >> 4, h = bh & 15;
    const int sg0 = q0 + w*16 + g, sg1 = sg0 + 8;
#pragma unroll
    for (int dt = 0; dt < 8; dt++) {
        int d = dt*8 + 2*tg;
        float2 v0 = make_float2(of[dt][0]*inv0, of[dt][1]*inv0);
        float2 v1 = make_float2(of[dt][2]*inv1, of[dt][3]*inv1);
        *(float2*)&ctx[((size_t)(b*SEQ + sg0) * NH + h) * DK + d] = v0;
        *(float2*)&ctx[((size_t)(b*SEQ + sg1) * NH + h) * DK + d] = v1;
    }
}

// ---------------------------------------------------------------------------
extern "C" void kernel_launch(void* const* d_in, const int* in_sizes, int n_in,
                              void* d_out, int out_size)
{
    const float* Xq = (const float*)d_in[0];
    const float* Xk = (const float*)d_in[1];
    const float* Xv = (const float*)d_in[2];
    const float* Wq = (const float*)d_in[3];
    const float* bq = (const float*)d_in[4];
    const float* Wk = (const float*)d_in[5];
    const float* bk = (const float*)d_in[6];
    const float* Wv = (const float*)d_in[7];
    const float* bv = (const float*)d_in[8];
    const float* Wo = (const float*)d_in[9];
    const float* bo = (const float*)d_in[10];
    float* out = (float*)d_out;

    float *Qp, *Kp, *Vp, *Cp;
    cudaGetSymbolAddress((void**)&Qp, g_Q);
    cudaGetSymbolAddress((void**)&Kp, g_K);
    cudaGetSymbolAddress((void**)&Vp, g_V);
    cudaGetSymbolAddress((void**)&Cp, g_ctx);

    cudaFuncSetAttribute(gemm_mma,
                         cudaFuncAttributeMaxDynamicSharedMemorySize,
                         GEMM_SMEM_BYTES);
    cudaFuncSetAttribute(attn_mma,
                         cudaFuncAttributeMaxDynamicSharedMemorySize,
                         ATTN_SMEM_BYTES);

    dim3 blk(256);

    // fused Q/K/V projections: blockIdx.z selects the triple
    dim3 gq(DM/64, MROWS/128, 3);    // 16 x 32 x 3
    gemm_mma<<<gq, blk, GEMM_SMEM_BYTES>>>(Xq, Xk, Xv, Wq, Wk, Wv,
                                           bq, bk, bv, Qp, Kp, Vp, 1);

    dim3 ga(SEQ/128, BATCH*NH);      // 16 x 32
    attn_mma<<<ga, blk, ATTN_SMEM_BYTES>>>(Qp, Kp, Vp, Cp);

    dim3 gp(DM/64, MROWS/128, 1);    // 16 x 32
    gemm_mma<<<gp, blk, GEMM_SMEM_BYTES>>>(Cp, Cp, Cp, Wo, Wo, Wo,
                                           bo, bo, bo, out, out, out, 0);
}